// round 10
// baseline (speedup 1.0000x reference)
#include <cuda_runtime.h>
#include <cstdint>

// Problem constants
#define HD  128     // hidden size
#define BBZ 512     // batch
#define LL  1000    // sequence length
#define NB  16      // batch rows per cluster
#define CLN 4       // CTAs per cluster
#define NTHREADS 256
#define KSTR 130    // weight row stride in floats (2 mod 32 -> conflict-free LDS.64)
#define GSTB (32 * KSTR * 4)   // gate stride in bytes within a weight matrix

// Shared memory layout (float offsets).
// Weights: [gate 0..3][unit 0..31][k 0..127], row stride KSTR.
// h buffers: [buf 0..1][batch 0..15][k 0..127] (k contiguous).
#define OFF_W1 0
#define OFF_W2 16640
#define OFF_W3 33280
#define OFF_H1 49920            // 2*16*128 = 4096 floats
#define OFF_H2 54016            // 2*16*128 = 4096 floats
#define SMEM_FLOATS 58112
#define SMEM_BYTES (SMEM_FLOATS * 4)   // 232448 B == smem opt-in cap

typedef unsigned long long u64t;

__device__ __forceinline__ float sigf(float v) {
    return __fdividef(1.f, 1.f + __expf(-v));
}
__device__ __forceinline__ float tanhf_fast(float v) {
    float a = fabsf(v);
    float e = __expf(-2.f * a);
    float r = __fdividef(1.f - e, 1.f + e);
    return copysignf(r, v);
}
__device__ __forceinline__ void cluster_bar() {
    asm volatile("barrier.cluster.arrive.aligned;" ::: "memory");
    asm volatile("barrier.cluster.wait.aligned;" ::: "memory");
}
__device__ __forceinline__ u64t lds64(uint32_t a) {
    u64t v; asm("ld.shared.b64 %0, [%1];" : "=l"(v) : "r"(a)); return v;
}
__device__ __forceinline__ void lds128x2(u64t& v0, u64t& v1, uint32_t a) {
    asm("ld.shared.v2.b64 {%0, %1}, [%2];" : "=l"(v0), "=l"(v1) : "r"(a));
}
__device__ __forceinline__ float lds32f(uint32_t a) {
    float v; asm("ld.shared.f32 %0, [%1];" : "=f"(v) : "r"(a)); return v;
}
__device__ __forceinline__ void sts32f(uint32_t a, float v) {
    asm volatile("st.shared.f32 [%0], %1;" :: "r"(a), "f"(v) : "memory");
}
__device__ __forceinline__ void ffma2(u64t& d, u64t a, u64t b) {
    asm("fma.rn.f32x2 %0, %1, %2, %0;" : "+l"(d) : "l"(a), "l"(b));
}
__device__ __forceinline__ float hadd2(u64t d) {
    float lo, hi;
    asm("mov.b64 {%0, %1}, %2;" : "=f"(lo), "=f"(hi) : "l"(d));
    return lo + hi;
}
__device__ __forceinline__ void pair_bar(int id) {
    asm volatile("bar.sync %0, 64;" :: "r"(id) : "memory");
}
__device__ __forceinline__ void st_cluster(uint32_t a, float v) {
    asm volatile("st.shared::cluster.f32 [%0], %1;" :: "r"(a), "f"(v) : "memory");
}

__global__ void __launch_bounds__(NTHREADS, 1) __cluster_dims__(CLN, 1, 1)
lstm_persistent_kernel(const float* __restrict__ x,
                       const float* __restrict__ w_ih1,
                       const float* __restrict__ w_hh1,
                       const float* __restrict__ b_ih1,
                       const float* __restrict__ b_hh1,
                       const float* __restrict__ w_ih2,
                       const float* __restrict__ w_hh2,
                       const float* __restrict__ b_ih2,
                       const float* __restrict__ b_hh2,
                       const float* __restrict__ w_lin,
                       const float* __restrict__ b_lin,
                       float* __restrict__ out)
{
    extern __shared__ float sm[];
    const int tid = threadIdx.x;
    uint32_t rank;
    asm("mov.u32 %0, %%cluster_ctarank;" : "=r"(rank));
    const int cid = blockIdx.x / CLN;
    const int batch0 = cid * NB;

    // ---- init: weight slices into smem, row-major per (gate,unit) ----
    for (int idx = tid; idx < 4 * 32 * HD; idx += NTHREADS) {
        int g = idx >> 12;
        int u5 = (idx >> 7) & 31;
        int k = idx & 127;
        int R = g * HD + (int)rank * 32 + u5;
        int o = (g * 32 + u5) * KSTR + k;
        sm[OFF_W1 + o] = w_hh1[R * HD + k];
        sm[OFF_W2 + o] = w_ih2[R * HD + k];
        sm[OFF_W3 + o] = w_hh2[R * HD + k];
    }
    for (int idx = tid; idx < 4096; idx += NTHREADS) {
        sm[OFF_H1 + idx] = 0.f;
        sm[OFF_H2 + idx] = 0.f;
    }

    // ---- per-thread assignment ----
    const int u  = tid & 31;          // hidden unit lane
    const int w  = tid >> 5;          // warp 0..7
    const int bg = w & 3;             // batch group (4 batches)
    const int ks = w >> 2;            // k-half: 0 -> k[0,64), 1 -> k[64,128)
    const int b0 = bg * 4;            // local batch base
    const int ob0 = b0 + 2 * ks;      // first OWNED local batch (2 owned)
    const int gu = (int)rank * 32 + u;
    const int kbase = ks * 64;

    // per-lane constants from gmem
    const float wi0 = w_ih1[0 * HD + gu], wi1 = w_ih1[1 * HD + gu];
    const float wi2 = w_ih1[2 * HD + gu], wi3 = w_ih1[3 * HD + gu];
    const float bA0 = b_ih1[0 * HD + gu] + b_hh1[0 * HD + gu];
    const float bA1 = b_ih1[1 * HD + gu] + b_hh1[1 * HD + gu];
    const float bA2 = b_ih1[2 * HD + gu] + b_hh1[2 * HD + gu];
    const float bA3 = b_ih1[3 * HD + gu] + b_hh1[3 * HD + gu];
    const float bB0 = b_ih2[0 * HD + gu] + b_hh2[0 * HD + gu];
    const float bB1 = b_ih2[1 * HD + gu] + b_hh2[1 * HD + gu];
    const float bB2 = b_ih2[2 * HD + gu] + b_hh2[2 * HD + gu];
    const float bB3 = b_ih2[3 * HD + gu] + b_hh2[3 * HD + gu];
    const float wl0 = w_lin[u], wl1 = w_lin[u + 32];
    const float wl2 = w_lin[u + 64], wl3 = w_lin[u + 96];
    const float blin = b_lin[0];

    float c1[2] = {0.f, 0.f};
    float c2[2] = {0.f, 0.f};

    const uint32_t sbase = (uint32_t)__cvta_generic_to_shared(sm);
    uint32_t peer[CLN];
#pragma unroll
    for (int r = 0; r < CLN; r++)
        asm("mapa.shared::cluster.u32 %0, %1, %2;" : "=r"(peer[r]) : "r"(sbase), "r"(r));

    // fixed per-thread addresses (bytes)
    const uint32_t w1base = sbase + (OFF_W1 + u * KSTR + kbase) * 4;
    const uint32_t w2base = sbase + (OFF_W2 + u * KSTR + kbase) * 4;
    const uint32_t w3base = sbase + (OFF_W3 + u * KSTR + kbase) * 4;
    const size_t xrow0 = (size_t)(batch0 + ob0) * LL;
    const size_t xrow1 = xrow0 + LL;

    cluster_bar();   // weights + zeroed h visible cluster-wide

    for (int t = 0; t < LL; ++t) {
        const int pbuf = t & 1, qbuf = pbuf ^ 1;

        // x for the 2 owned batches (LDG early; consumed in epilogue)
        const float xv0 = x[xrow0 + t];
        const float xv1 = x[xrow1 + t];

        // ================= layer 1 matvec: Whh1 @ h1[qbuf] over k-half =========
        u64t acc[4][4];
#pragma unroll
        for (int g = 0; g < 4; g++)
#pragma unroll
            for (int b = 0; b < 4; b++) acc[g][b] = 0ULL;
        {
            const uint32_t hqb = sbase + (OFF_H1 + qbuf * 2048 + b0 * 128 + kbase) * 4;
#pragma unroll 4
            for (int i = 0; i < 16; ++i) {
                const uint32_t wo = w1base + i * 16;
                u64t wp[4][2];
#pragma unroll
                for (int g = 0; g < 4; g++) {
                    wp[g][0] = lds64(wo + g * GSTB);
                    wp[g][1] = lds64(wo + g * GSTB + 8);
                }
#pragma unroll
                for (int b = 0; b < 4; b++) {
                    u64t h0, h1v;
                    lds128x2(h0, h1v, hqb + b * 512 + i * 16);
#pragma unroll
                    for (int g = 0; g < 4; g++) {
                        ffma2(acc[g][b], wp[g][0], h0);
                        ffma2(acc[g][b], wp[g][1], h1v);
                    }
                }
            }
        }
        // ---- k-reduction exchange (scratch = dead region h2[pbuf]) ----
        float s[4][4];
#pragma unroll
        for (int g = 0; g < 4; g++)
#pragma unroll
            for (int b = 0; b < 4; b++) s[g][b] = hadd2(acc[g][b]);
        {
            const uint32_t scr = sbase + (OFF_H2 + pbuf * 2048) * 4;
#pragma unroll
            for (int j = 0; j < 2; j++) {
                const int bl = (ks ^ 1) * 2 + j;    // non-owned local batch
#pragma unroll
                for (int g = 0; g < 4; g++)
                    sts32f(scr + ((((w * 2 + j) * 4 + g) * 32 + u) << 2), s[g][bl]);
            }
            pair_bar(bg + 1);
#pragma unroll
            for (int j = 0; j < 2; j++) {
                const int bl = ks * 2 + j;          // owned local batch
#pragma unroll
                for (int g = 0; g < 4; g++)
                    s[g][bl] += lds32f(scr + (((((w ^ 4) * 2 + j) * 4 + g) * 32 + u) << 2));
            }
        }
        // ---- layer-1 cell for 2 owned batches + cluster broadcast of h1 ----
        {
#pragma unroll
            for (int j = 0; j < 2; j++) {
                const int bl = ks * 2 + j;
                const float xv = j ? xv1 : xv0;
                float pi = fmaf(xv, wi0, s[0][bl]) + bA0;
                float pf = fmaf(xv, wi1, s[1][bl]) + bA1;
                float pg = fmaf(xv, wi2, s[2][bl]) + bA2;
                float po = fmaf(xv, wi3, s[3][bl]) + bA3;
                float ig = sigf(pi), fg = sigf(pf), gg = tanhf_fast(pg), og = sigf(po);
                float c = fmaf(fg, c1[j], ig * gg);
                c1[j] = c;
                float h = og * tanhf_fast(c);
                const uint32_t off = (uint32_t)((OFF_H1 + (pbuf * NB + ob0 + j) * 128 + gu) * 4);
#pragma unroll
                for (int r = 0; r < CLN; r++) st_cluster(peer[r] + off, h);
            }
        }
        cluster_bar();   // h1[pbuf] complete cluster-wide

        // ================= layer 2 matvec: Wih2@h1[pbuf] + Whh2@h2[qbuf] =========
#pragma unroll
        for (int g = 0; g < 4; g++)
#pragma unroll
            for (int b = 0; b < 4; b++) acc[g][b] = 0ULL;
        {
            const uint32_t h1p = sbase + (OFF_H1 + pbuf * 2048 + b0 * 128 + kbase) * 4;
            const uint32_t h2q = sbase + (OFF_H2 + qbuf * 2048 + b0 * 128 + kbase) * 4;
#pragma unroll 2
            for (int i = 0; i < 16; ++i) {
                const uint32_t wo2 = w2base + i * 16;
                const uint32_t wo3 = w3base + i * 16;
                u64t wp2[4][2], wp3[4][2];
#pragma unroll
                for (int g = 0; g < 4; g++) {
                    wp2[g][0] = lds64(wo2 + g * GSTB);
                    wp2[g][1] = lds64(wo2 + g * GSTB + 8);
                    wp3[g][0] = lds64(wo3 + g * GSTB);
                    wp3[g][1] = lds64(wo3 + g * GSTB + 8);
                }
#pragma unroll
                for (int b = 0; b < 4; b++) {
                    u64t p0, p1, q0, q1;
                    lds128x2(p0, p1, h1p + b * 512 + i * 16);
                    lds128x2(q0, q1, h2q + b * 512 + i * 16);
#pragma unroll
                    for (int g = 0; g < 4; g++) {
                        ffma2(acc[g][b], wp2[g][0], p0);
                        ffma2(acc[g][b], wp2[g][1], p1);
                        ffma2(acc[g][b], wp3[g][0], q0);
                        ffma2(acc[g][b], wp3[g][1], q1);
                    }
                }
            }
        }
        // ---- k-reduction exchange (scratch = dead region h1[qbuf]) ----
#pragma unroll
        for (int g = 0; g < 4; g++)
#pragma unroll
            for (int b = 0; b < 4; b++) s[g][b] = hadd2(acc[g][b]);
        {
            const uint32_t scr = sbase + (OFF_H1 + qbuf * 2048) * 4;
#pragma unroll
            for (int j = 0; j < 2; j++) {
                const int bl = (ks ^ 1) * 2 + j;
#pragma unroll
                for (int g = 0; g < 4; g++)
                    sts32f(scr + ((((w * 2 + j) * 4 + g) * 32 + u) << 2), s[g][bl]);
            }
            pair_bar(bg + 1);
#pragma unroll
            for (int j = 0; j < 2; j++) {
                const int bl = ks * 2 + j;
#pragma unroll
                for (int g = 0; g < 4; g++)
                    s[g][bl] += lds32f(scr + (((((w ^ 4) * 2 + j) * 4 + g) * 32 + u) << 2));
            }
        }
        // ---- layer-2 cell for 2 owned batches + cluster broadcast of h2 ----
        {
#pragma unroll
            for (int j = 0; j < 2; j++) {
                const int bl = ks * 2 + j;
                float pi = s[0][bl] + bB0;
                float pf = s[1][bl] + bB1;
                float pg = s[2][bl] + bB2;
                float po = s[3][bl] + bB3;
                float ig = sigf(pi), fg = sigf(pf), gg = tanhf_fast(pg), og = sigf(po);
                float c = fmaf(fg, c2[j], ig * gg);
                c2[j] = c;
                float h = og * tanhf_fast(c);
                const uint32_t off = (uint32_t)((OFF_H2 + (pbuf * NB + ob0 + j) * 128 + gu) * 4);
#pragma unroll
                for (int r = 0; r < CLN; r++) st_cluster(peer[r] + off, h);
            }
        }
        cluster_bar();   // h2[pbuf] complete cluster-wide

        // ---------- output head: each warp emits its 2 owned batches ----------
        {
            const float* __restrict__ hpA = sm + OFF_H2 + pbuf * 2048 + (ob0) * 128;
            const float* __restrict__ hpB = hpA + 128;
            float d0 = hpA[u] * wl0 + hpA[u + 32] * wl1 + hpA[u + 64] * wl2 + hpA[u + 96] * wl3;
            float d1 = hpB[u] * wl0 + hpB[u + 32] * wl1 + hpB[u + 64] * wl2 + hpB[u + 96] * wl3;
#pragma unroll
            for (int m = 16; m >= 1; m >>= 1) {
                d0 += __shfl_xor_sync(0xffffffffu, d0, m);
                d1 += __shfl_xor_sync(0xffffffffu, d1, m);
            }
            if (u == 0) {
                out[xrow0 + t] = d0 + blin;
                out[xrow1 + t] = d1 + blin;
            }
        }
    }
}

extern "C" void kernel_launch(void* const* d_in, const int* in_sizes, int n_in,
                              void* d_out, int out_size)
{
    (void)in_sizes; (void)n_in; (void)out_size;
    cudaFuncSetAttribute(lstm_persistent_kernel,
                         cudaFuncAttributeMaxDynamicSharedMemorySize, SMEM_BYTES);
    lstm_persistent_kernel<<<(BBZ / NB) * CLN, NTHREADS, SMEM_BYTES>>>(
        (const float*)d_in[0],   // x
        (const float*)d_in[1],   // w_ih1
        (const float*)d_in[2],   // w_hh1
        (const float*)d_in[3],   // b_ih1
        (const float*)d_in[4],   // b_hh1
        (const float*)d_in[5],   // w_ih2
        (const float*)d_in[6],   // w_hh2
        (const float*)d_in[7],   // b_ih2
        (const float*)d_in[8],   // b_hh2
        (const float*)d_in[9],   // w_lin
        (const float*)d_in[10],  // b_lin
        (float*)d_out);
}